// round 17
// baseline (speedup 1.0000x reference)
#include <cuda_runtime.h>
#include <cuda_fp16.h>
#include <stdint.h>

#define TPB   256
#define NNODE 49
#define DIM   768
#define C1    256
#define C2    128
#define NCLS  13
#define NST1  24           // 768/32 K32 stages
#define NST2  8            // 256/32

#define SROW 80            // stage tile row stride bytes -> conflict-free LDSM
#define SH   264           // H1 row stride (fp16 elems) = 528B
#define DSH  264           // d1h row stride (fp16 elems)
#define SRA  144           // ADJ row stride bytes (64 fp16 + pad) -> conflict-free LDSM

// ---- GEMM1 stage layout (bytes within stage) ----
#define A_T  0             // 64 x 80 (fp16)
#define B_T  5120          // 256 x 80 (fp16)
#define STG  25600         // x4 stages: [0, 102400)
// ---- phase-2 layout (aliases stage region; GEMM1 retired first) ----
#define OFF_H1   0         // 64 x 264 fp16 = 33792
#define OFF_D1S  33792     // 64 x 264 fp16 = 33792 -> 67584
#define OFF_B2   67584     // 2 stages x 10240 -> 88064
#define B2_STG   10240
// ---- persistent (no alias) ----
#define OFF_ADJ  102400    // 64 x 144 B = 9216 -> 111616
#define OFF_DINV 111616    // 256
#define OFF_POOL 111872    // 128 fp32 = 512
#define SMEM_BYTES 112640

// ---- pre-converted weights (filled by prep kernel) ----
__device__ __half g_W1[C1 * DIM];
__device__ __half g_W2[C2 * C1];

__device__ __forceinline__ void mma_f16(float* c, const unsigned* a, const unsigned* b) {
    asm volatile(
        "mma.sync.aligned.m16n8k16.row.col.f32.f16.f16.f32 "
        "{%0,%1,%2,%3}, {%4,%5,%6,%7}, {%8,%9}, {%0,%1,%2,%3};\n"
        : "+f"(c[0]), "+f"(c[1]), "+f"(c[2]), "+f"(c[3])
        : "r"(a[0]), "r"(a[1]), "r"(a[2]), "r"(a[3]), "r"(b[0]), "r"(b[1]));
}
__device__ __forceinline__ void ldsm4(unsigned* r, uint32_t addr) {
    asm volatile("ldmatrix.sync.aligned.m8n8.x4.shared.b16 {%0,%1,%2,%3}, [%4];"
        : "=r"(r[0]), "=r"(r[1]), "=r"(r[2]), "=r"(r[3]) : "r"(addr));
}
__device__ __forceinline__ void ldsm4t(unsigned* r, uint32_t addr) {
    asm volatile("ldmatrix.sync.aligned.m8n8.x4.trans.shared.b16 {%0,%1,%2,%3}, [%4];"
        : "=r"(r[0]), "=r"(r[1]), "=r"(r[2]), "=r"(r[3]) : "r"(addr));
}
__device__ __forceinline__ void cpa16(uint32_t dst, const void* src) {
    asm volatile("cp.async.cg.shared.global [%0], [%1], 16;" :: "r"(dst), "l"(src));
}
#define CPA_COMMIT() asm volatile("cp.async.commit_group;" ::: "memory")
#define CPA_WAIT0()  asm volatile("cp.async.wait_group 0;" ::: "memory")

__device__ __forceinline__ unsigned packh(__half a, __half b) {
    return ((unsigned)__half_as_ushort(b) << 16) | (unsigned)__half_as_ushort(a);
}
__device__ __forceinline__ unsigned packf(float a, float b) {
    return packh(__float2half(a), __float2half(b));
}

// ==================== prep: convert + transpose weights ====================
__global__ void prep_weights(const float* __restrict__ W1, const float* __restrict__ W2) {
    int idx = blockIdx.x * blockDim.x + threadIdx.x;
    if (idx < C1 * DIM) {                       // W1 [768][256] -> [256][768]
        int k = idx >> 8, n = idx & 255;
        g_W1[n * DIM + k] = __float2half(W1[idx]);
    } else if (idx < C1 * DIM + C1 * C2) {      // W2 [256][128] -> [128][256]
        int j = idx - C1 * DIM;
        int k = j >> 7, n = j & 127;
        g_W2[n * C1 + k] = __float2half(W2[j]);
    }
}

// =========================== main fused kernel ===========================
__global__ void __launch_bounds__(TPB, 2)
gnn_fused(const float* __restrict__ x,  const float* __restrict__ b1,
          const float* __restrict__ b2, const float* __restrict__ Wf,
          const float* __restrict__ bf, float* __restrict__ out)
{
    extern __shared__ unsigned char smem[];
    const uint32_t sbase = (uint32_t)__cvta_generic_to_shared(smem);

    float*  dinv   = (float*)(smem + OFF_DINV);
    float*  pooled = (float*)(smem + OFF_POOL);
    __half* d1h    = (__half*)(smem + OFF_D1S);
    __half* adjm   = (__half*)(smem + OFF_ADJ);

    const int tid  = threadIdx.x;
    const int lane = tid & 31;
    const int wid  = tid >> 5;    // 0..7
    const int wm   = wid >> 2;    // 0..1  (m32 block)
    const int wn   = wid & 3;     // 0..3  (n64 G1 / n32 G2/ADJ)
    const int tr   = lane >> 2;
    const int tc   = lane & 3;
    const int b0   = blockIdx.x;  // one graph per CTA

    // ldmatrix lane patterns
    const int lrow  = (lane & 7) + ((lane >> 3) & 1) * 8;  // normal
    const int lkb   = (lane >> 4) * 16;
    const int krowB = (lane & 7) + ((lane >> 4) & 1) * 8;  // trans
    const int nbB   = ((lane >> 3) & 1) * 16;

    // ---- dinv + pooled init ----
    if (tid < NNODE) {
        int r = tid / 7, c = tid % 7;
        int nr = min(r + 1, 6) - max(r - 1, 0) + 1;
        int nc = min(c + 1, 6) - max(c - 1, 0) + 1;
        dinv[tid] = 1.0f / sqrtf((float)(nr * nc));
    }
    if (tid < C2) pooled[tid] = 0.0f;
    __syncthreads();
    // ---- build fp16 ADJ [64 x 64] ----
    for (int idx = tid; idx < 64 * 64; idx += TPB) {
        const int i = idx >> 6, j = idx & 63;
        float w = 0.0f;
        if (i < NNODE && j < NNODE) {
            const int ri = i / 7, ci = i % 7, rj = j / 7, cj = j % 7;
            if (abs(ri - rj) <= 1 && abs(ci - cj) <= 1) w = dinv[i] * dinv[j];
        }
        adjm[i * (SRA / 2) + j] = __float2half(w);
    }

    // ---- staging thread assignments (256 threads) ----
    const int arow = tid >> 2;          // 0..63
    const int ac   = tid & 3;
    const bool aval = (arow < NNODE);
    const float* pxa = x + ((size_t)b0 * NNODE + min(arow, NNODE - 1)) * DIM + ac * 8;
    const uint32_t adst = (uint32_t)(arow * SROW + ac * 16);
    const __half* pw1 = g_W1 + (size_t)tid * DIM;      // n = tid, 4 chunks
    const uint32_t bdst = (uint32_t)(B_T + tid * SROW);

    // frag base byte offsets
    const uint32_t aoff = (uint32_t)((wm * 32 + lrow) * SROW + lkb);
    const uint32_t boff = (uint32_t)((wn * 64 + lrow) * SROW + lkb);

    // ---- stage helpers ----
    auto ldA = [&](int kt, uint4& r) {
        if (aval) {
            float4 a = *(const float4*)(pxa + kt * 32);
            float4 b = *(const float4*)(pxa + kt * 32 + 4);
            r.x = packf(a.x, a.y); r.y = packf(a.z, a.w);
            r.z = packf(b.x, b.y); r.w = packf(b.z, b.w);
        } else r = make_uint4(0, 0, 0, 0);
    };
    auto stsA = [&](uint32_t stg, const uint4& v) {
        asm volatile("st.shared.v4.b32 [%0], {%1,%2,%3,%4};"
                     :: "r"(sbase + stg + A_T + adst),
                        "r"(v.x), "r"(v.y), "r"(v.z), "r"(v.w) : "memory");
    };
    auto fillB = [&](int kt, uint32_t stg) {
        const int ke = kt * 32;
        #pragma unroll
        for (int c = 0; c < 4; c++)
            cpa16(sbase + stg + bdst + c * 16, pw1 + ke + c * 8);
        CPA_COMMIT();
    };

    // ===== GEMM1: T1 = X @ W1  (64 x 256 x 768, fp16, pair-stage) =====
    float acc[16][4];
    #pragma unroll
    for (int j = 0; j < 16; j++)
        #pragma unroll
        for (int k = 0; k < 4; k++) acc[j][k] = 0.0f;

    auto compute1 = [&](int kt) {
        const uint32_t cs = (uint32_t)(kt & 3) * STG;
        #pragma unroll
        for (int kh = 0; kh < 2; kh++) {
            unsigned af[2][4];
            #pragma unroll
            for (int mi = 0; mi < 2; mi++)
                ldsm4(af[mi], sbase + cs + A_T + aoff + mi * 16 * SROW + kh * 32);
            #pragma unroll
            for (int p = 0; p < 4; p++) {
                unsigned bh4[4];
                ldsm4(bh4, sbase + cs + B_T + boff + p * 16 * SROW + kh * 32);
                #pragma unroll
                for (int h = 0; h < 2; h++) {
                    const int nj = p * 2 + h;
                    unsigned bh[2] = { bh4[h], bh4[2 + h] };
                    #pragma unroll
                    for (int mi = 0; mi < 2; mi++)
                        mma_f16(acc[mi*8+nj], af[mi], bh);
                }
            }
        }
    };

    uint4 rP0, rP1;
    {
        uint4 t0, t1;
        ldA(0, t0); ldA(1, t1);
        stsA(0, t0); stsA(STG, t1);
        fillB(0, 0); fillB(1, STG);
        ldA(2, rP0); ldA(3, rP1);
    }

    #pragma unroll 1
    for (int kt = 0; kt < NST1; kt += 2) {
        CPA_WAIT0();
        __syncthreads();
        if (kt + 2 < NST1) {
            const uint32_t n0 = (uint32_t)((kt + 2) & 3) * STG;
            const uint32_t n1 = (uint32_t)((kt + 3) & 3) * STG;
            stsA(n0, rP0); fillB(kt + 2, n0);
            stsA(n1, rP1); fillB(kt + 3, n1);
            if (kt + 4 < NST1) { ldA(kt + 4, rP0); ldA(kt + 5, rP1); }
        }
        compute1(kt);
        compute1(kt + 1);
    }
    __syncthreads();

    // GEMM2 B staging: 128 n x 4 chunks = 512 ops -> 2 per thread
    const int b2n  = tid >> 1;
    const int b2c0 = (tid & 1) * 2;
    const __half* pw2 = g_W2 + (size_t)b2n * C1 + b2c0 * 8;
    const uint32_t b2dst = (uint32_t)(b2n * SROW + b2c0 * 16);
    auto fill2 = [&](int kt) {
        #pragma unroll
        for (int c = 0; c < 2; c++)
            cpa16(sbase + OFF_B2 + (uint32_t)(kt & 1) * B2_STG + b2dst + c * 16,
                  pw2 + kt * 32 + c * 8);
        CPA_COMMIT();
    };

    // ===== epilogue 1 (tensorized): store T1, ADJ-GEMM, bias+relu -> H1 =====
    __half* H1 = (__half*)(smem + OFF_H1);
    {
        #pragma unroll
        for (int mi = 0; mi < 2; mi++)
            #pragma unroll
            for (int nj = 0; nj < 8; nj++) {
                const int row = wm*32 + mi*16 + tr;
                const int col = wn*64 + nj*8 + tc*2;
                float* a = acc[mi*8+nj];
                *(unsigned*)(d1h + row * DSH + col)       = packf(a[0], a[1]);
                *(unsigned*)(d1h + (row + 8) * DSH + col) = packf(a[2], a[3]);
            }
        fill2(0);                  // prefetch GEMM2 B stage 0
        __syncthreads();

        const uint32_t adjA = sbase + OFF_ADJ + (uint32_t)((wm*32 + lrow) * SRA + lkb);
        const uint32_t btB  = sbase + OFF_D1S + (uint32_t)(krowB * (DSH*2) + nbB);

        #pragma unroll 1
        for (int ci = 0; ci < 2; ci++) {
            float e[8][4];
            #pragma unroll
            for (int j = 0; j < 8; j++)
                #pragma unroll
                for (int k = 0; k < 4; k++) e[j][k] = 0.0f;
            #pragma unroll
            for (int kt = 0; kt < 4; kt++) {
                unsigned aA[2][4];
                #pragma unroll
                for (int mi = 0; mi < 2; mi++)
                    ldsm4(aA[mi], adjA + mi*16*SRA + kt*32);
                #pragma unroll
                for (int p = 0; p < 2; p++) {
                    unsigned bt4[4];
                    ldsm4t(bt4, btB + kt*16*(DSH*2) + (uint32_t)(ci*128 + wn*32 + p*16)*2);
                    #pragma unroll
                    for (int h = 0; h < 2; h++) {
                        unsigned bh[2] = { bt4[h], bt4[2+h] };
                        #pragma unroll
                        for (int mi = 0; mi < 2; mi++)
                            mma_f16(e[mi*4 + p*2 + h], aA[mi], bh);
                    }
                }
            }
            #pragma unroll
            for (int mi = 0; mi < 2; mi++)
                #pragma unroll
                for (int nj = 0; nj < 4; nj++) {
                    const int row = wm*32 + mi*16 + tr;
                    const int col = ci*128 + wn*32 + nj*8 + tc*2;
                    float2 bb = __ldg((const float2*)(b1 + col));
                    float* v = e[mi*4+nj];
                    *(unsigned*)(H1 + row * SH + col) =
                        packf(fmaxf(v[0] + bb.x, 0.f), fmaxf(v[1] + bb.y, 0.f));
                    *(unsigned*)(H1 + (row + 8) * SH + col) =
                        packf(fmaxf(v[2] + bb.x, 0.f), fmaxf(v[3] + bb.y, 0.f));
                }
        }
        __syncthreads();
    }

    // ===== GEMM2: T2 = H1 @ W2  (64 x 128 x 256, fp16, 2-stage) =====
    float acc2[8][4];
    #pragma unroll
    for (int j = 0; j < 8; j++)
        #pragma unroll
        for (int k = 0; k < 4; k++) acc2[j][k] = 0.0f;

    const uint32_t hoff  = (uint32_t)((wm * 32 + lrow) * (SH * 2) + lkb);
    const uint32_t b2off = (uint32_t)((wn * 32 + lrow) * SROW + lkb);

    #pragma unroll 1
    for (int kt = 0; kt < NST2; kt++) {
        const uint32_t cs = OFF_B2 + (uint32_t)(kt & 1) * B2_STG;
        CPA_WAIT0();
        __syncthreads();
        if (kt + 1 < NST2) fill2(kt + 1);
        #pragma unroll
        for (int kh = 0; kh < 2; kh++) {
            unsigned af[2][4];
            #pragma unroll
            for (int mi = 0; mi < 2; mi++)
                ldsm4(af[mi], sbase + OFF_H1 + hoff + mi*16*(SH*2) + kt*64 + kh*32);
            #pragma unroll
            for (int p = 0; p < 2; p++) {
                unsigned bh4[4];
                ldsm4(bh4, sbase + cs + b2off + p*16*SROW + kh*32);
                #pragma unroll
                for (int h = 0; h < 2; h++) {
                    const int nj = p*2 + h;
                    unsigned bh[2] = { bh4[h], bh4[2+h] };
                    #pragma unroll
                    for (int mi = 0; mi < 2; mi++)
                        mma_f16(acc2[mi*4+nj], af[mi], bh);
                }
            }
        }
    }
    __syncthreads();

    // ===== epilogue 2 (tensorized): store T2, ADJ-GEMM, masked relu-pool =====
    {
        #pragma unroll
        for (int mi = 0; mi < 2; mi++)
            #pragma unroll
            for (int nj = 0; nj < 4; nj++) {
                const int row = wm*32 + mi*16 + tr;
                const int col = wn*32 + nj*8 + tc*2;
                float* a = acc2[mi*4+nj];
                *(unsigned*)(d1h + row * DSH + col)       = packf(a[0], a[1]);
                *(unsigned*)(d1h + (row + 8) * DSH + col) = packf(a[2], a[3]);
            }
        __syncthreads();

        const uint32_t adjA = sbase + OFF_ADJ + (uint32_t)((wm*32 + lrow) * SRA + lkb);
        const uint32_t btB  = sbase + OFF_D1S + (uint32_t)(krowB * (DSH*2) + nbB);

        float e[8][4];
        #pragma unroll
        for (int j = 0; j < 8; j++)
            #pragma unroll
            for (int k = 0; k < 4; k++) e[j][k] = 0.0f;
        #pragma unroll
        for (int kt = 0; kt < 4; kt++) {
            unsigned aA[2][4];
            #pragma unroll
            for (int mi = 0; mi < 2; mi++)
                ldsm4(aA[mi], adjA + mi*16*SRA + kt*32);
            #pragma unroll
            for (int p = 0; p < 2; p++) {
                unsigned bt4[4];
                ldsm4t(bt4, btB + kt*16*(DSH*2) + (uint32_t)(wn*32 + p*16)*2);
                #pragma unroll
                for (int h = 0; h < 2; h++) {
                    unsigned bh[2] = { bt4[h], bt4[2+h] };
                    #pragma unroll
                    for (int mi = 0; mi < 2; mi++)
                        mma_f16(e[mi*4 + p*2 + h], aA[mi], bh);
                }
            }
        }
        #pragma unroll
        for (int nj = 0; nj < 4; nj++) {
            const int col = wn*32 + nj*8 + tc*2;
            float2 bb = __ldg((const float2*)(b2 + col));
            float s0 = 0.0f, s1 = 0.0f;
            #pragma unroll
            for (int mi = 0; mi < 2; mi++) {
                const int r = wm*32 + mi*16 + tr;
                float* v = e[mi*4+nj];
                if (r < NNODE) {
                    s0 += fmaxf(v[0] + bb.x, 0.f);
                    s1 += fmaxf(v[1] + bb.y, 0.f);
                }
                if (r + 8 < NNODE) {
                    s0 += fmaxf(v[2] + bb.x, 0.f);
                    s1 += fmaxf(v[3] + bb.y, 0.f);
                }
            }
            s0 += __shfl_xor_sync(0xFFFFFFFFu, s0, 4);
            s1 += __shfl_xor_sync(0xFFFFFFFFu, s1, 4);
            s0 += __shfl_xor_sync(0xFFFFFFFFu, s0, 8);
            s1 += __shfl_xor_sync(0xFFFFFFFFu, s1, 8);
            s0 += __shfl_xor_sync(0xFFFFFFFFu, s0, 16);
            s1 += __shfl_xor_sync(0xFFFFFFFFu, s1, 16);
            if (tr == 0) {
                atomicAdd(&pooled[col], s0);
                atomicAdd(&pooled[col + 1], s1);
            }
        }
        __syncthreads();
    }

    if (tid < NCLS) {
        float dot = 0.0f;
        #pragma unroll 8
        for (int k = 0; k < C2; k++) dot += pooled[k] * __ldg(&Wf[k * NCLS + tid]);
        out[(size_t)b0 * NCLS + tid] = __ldg(&bf[tid]) + dot * (1.0f / 49.0f);
    }
}

extern "C" void kernel_launch(void* const* d_in, const int* in_sizes, int n_in,
                              void* d_out, int out_size)
{
    const float* x  = (const float*)d_in[0];
    const float* W1 = (const float*)d_in[1];
    const float* b1 = (const float*)d_in[2];
    const float* W2 = (const float*)d_in[3];
    const float* b2 = (const float*)d_in[4];
    const float* Wf = (const float*)d_in[5];
    const float* bf = (const float*)d_in[6];
    float* out = (float*)d_out;

    const int B = in_sizes[0] / (NNODE * DIM);   // 4096

    prep_weights<<<(C1 * DIM + C1 * C2 + 255) / 256, 256>>>(W1, W2);

    cudaFuncSetAttribute(gnn_fused, cudaFuncAttributeMaxDynamicSharedMemorySize, SMEM_BYTES);
    gnn_fused<<<B, TPB, SMEM_BYTES>>>(x, b1, b2, Wf, bf, out);
}